// round 2
// baseline (speedup 1.0000x reference)
#include <cuda_runtime.h>
#include <cstdint>

#define NU 200000
#define NI 100000
#define NE 3200000
#define DD 64

// ---------------- device scratch (static; no runtime allocation) ----------------
__device__ float g_hu[NU * DD];      // layer-0 output for users
__device__ float g_hi[NI * DD];      // layer-0 output for items
__device__ float g_agg_u[NU * DD];   // aggregated (sum) at users
__device__ float g_agg_i[NI * DD];   // aggregated (sum) at items
__device__ int   g_cnt_u[NU];
__device__ int   g_cnt_i[NI];
__device__ int   g_off_u[NU + 1];
__device__ int   g_off_i[NI + 1];
__device__ int   g_woff_u[NU];
__device__ int   g_woff_i[NI];
__device__ int   g_ssrc_u2i[NE];     // CSR by item-dst: source user ids
__device__ int   g_ssrc_i2u[NE];     // CSR by user-dst: source item ids
__device__ int   g_bsum_u[256];
__device__ int   g_bsum_i[256];

// ---------------- small utility kernels ----------------
__global__ void zero_int_k(int* __restrict__ p, int n) {
    int i = blockIdx.x * blockDim.x + threadIdx.x;
    if (i < n) p[i] = 0;
}

__global__ void count_k(const int* __restrict__ dst, int* __restrict__ cnt, int n) {
    for (int i = blockIdx.x * blockDim.x + threadIdx.x; i < n; i += gridDim.x * blockDim.x)
        atomicAdd(&cnt[__ldg(&dst[i])], 1);
}

// ---------------- 3-kernel exclusive scan (counts -> row offsets) ----------------
__global__ void block_sum_k(const int* __restrict__ cnt, int* __restrict__ bsum, int n) {
    __shared__ int s[1024];
    int i = blockIdx.x * 1024 + threadIdx.x;
    int v = (i < n) ? cnt[i] : 0;
    s[threadIdx.x] = v;
    __syncthreads();
    for (int st = 512; st > 0; st >>= 1) {
        if (threadIdx.x < st) s[threadIdx.x] += s[threadIdx.x + st];
        __syncthreads();
    }
    if (threadIdx.x == 0) bsum[blockIdx.x] = s[0];
}

__global__ void scan_bsum_k(int* __restrict__ bsum, int nb) {
    __shared__ int s[1024];
    int v = (threadIdx.x < nb) ? bsum[threadIdx.x] : 0;
    s[threadIdx.x] = v;
    __syncthreads();
    for (int o = 1; o < 1024; o <<= 1) {
        int t = (threadIdx.x >= o) ? s[threadIdx.x - o] : 0;
        __syncthreads();
        s[threadIdx.x] += t;
        __syncthreads();
    }
    if (threadIdx.x < nb) bsum[threadIdx.x] = s[threadIdx.x] - v;  // exclusive
}

__global__ void scan_write_k(const int* __restrict__ cnt, const int* __restrict__ bsum,
                             int* __restrict__ off, int* __restrict__ woff, int n) {
    __shared__ int s[1024];
    int i = blockIdx.x * 1024 + threadIdx.x;
    int v = (i < n) ? cnt[i] : 0;
    s[threadIdx.x] = v;
    __syncthreads();
    for (int o = 1; o < 1024; o <<= 1) {
        int t = (threadIdx.x >= o) ? s[threadIdx.x - o] : 0;
        __syncthreads();
        s[threadIdx.x] += t;
        __syncthreads();
    }
    int excl = s[threadIdx.x] - v + bsum[blockIdx.x];
    if (i < n) { off[i] = excl; woff[i] = excl; }
    if (i == n - 1) off[n] = excl + v;
}

__global__ void fill_k(const int* __restrict__ src, const int* __restrict__ dst,
                       int* __restrict__ woff, int* __restrict__ ssrc, int n) {
    for (int i = blockIdx.x * blockDim.x + threadIdx.x; i < n; i += gridDim.x * blockDim.x) {
        int d = __ldg(&dst[i]);
        int p = atomicAdd(&woff[d], 1);
        ssrc[p] = __ldg(&src[i]);
    }
}

// ---------------- aggregation: gather-at-destination (no float atomics) ----------------
// 16 threads per destination node; each owns one float4 slot of the 64-dim feature.
__global__ void agg_k(const float* __restrict__ h, const int* __restrict__ roff,
                      const int* __restrict__ ssrc, float* __restrict__ agg, int n) {
    int t = blockIdx.x * blockDim.x + threadIdx.x;
    int node = t >> 4;
    if (node >= n) return;
    int q = (t & 15) << 2;
    int b0 = __ldg(&roff[node]), b1 = __ldg(&roff[node + 1]);
    float4 acc = make_float4(0.f, 0.f, 0.f, 0.f);
    int i = b0;
    for (; i + 4 <= b1; i += 4) {
        int s0 = __ldg(&ssrc[i]), s1 = __ldg(&ssrc[i + 1]);
        int s2 = __ldg(&ssrc[i + 2]), s3 = __ldg(&ssrc[i + 3]);
        float4 v0 = *(const float4*)(h + (size_t)s0 * DD + q);
        float4 v1 = *(const float4*)(h + (size_t)s1 * DD + q);
        float4 v2 = *(const float4*)(h + (size_t)s2 * DD + q);
        float4 v3 = *(const float4*)(h + (size_t)s3 * DD + q);
        acc.x += (v0.x + v1.x) + (v2.x + v3.x);
        acc.y += (v0.y + v1.y) + (v2.y + v3.y);
        acc.z += (v0.z + v1.z) + (v2.z + v3.z);
        acc.w += (v0.w + v1.w) + (v2.w + v3.w);
    }
    for (; i < b1; i++) {
        int s = __ldg(&ssrc[i]);
        float4 v = *(const float4*)(h + (size_t)s * DD + q);
        acc.x += v.x; acc.y += v.y; acc.z += v.z; acc.w += v.w;
    }
    *(float4*)(agg + (size_t)node * DD + q) = acc;
}

// ---------------- fused GEMM + bias + residual + LayerNorm + ReLU ----------------
// out = relu(LN(agg/cnt @ Wrel + h @ Wroot + b + h))
// Tile = 32 nodes. Thread (d = tid&63, ty = tid>>6) computes 8 nodes for output dim d.
__global__ __launch_bounds__(256, 4) void compute_k(
    const float* __restrict__ agg, const int* __restrict__ cnt,
    const float* __restrict__ h,
    const float* __restrict__ Wrel, const float* __restrict__ Wroot,
    const float* __restrict__ bias, const float* __restrict__ gam,
    const float* __restrict__ bet,
    float* __restrict__ out, int n) {
    __shared__ float sW0[4096];
    __shared__ float sW1[4096];
    __shared__ float sIn0[2048];   // scaled agg; reused as pre-LN output stage
    __shared__ float sIn1[2048];   // h (root input + residual)
    int tid = threadIdx.x;
    for (int i = tid; i < 4096; i += 256) { sW0[i] = Wrel[i]; sW1[i] = Wroot[i]; }
    int d = tid & 63;
    int ty = tid >> 6;
    float bd = __ldg(&bias[d]);
    int lane = tid & 31, wid = tid >> 5;
    float gg0 = __ldg(&gam[lane]), gg1 = __ldg(&gam[lane + 32]);
    float bb0 = __ldg(&bet[lane]), bb1 = __ldg(&bet[lane + 32]);
    int ntile = n >> 5;  // n is a multiple of 32 for both node sets
    for (int tile = blockIdx.x; tile < ntile; tile += gridDim.x) {
        int base = tile << 5;
        __syncthreads();
        // stage 32 nodes x (agg/cnt , h) into smem, float4 granularity
        for (int i = tid; i < 512; i += 256) {
            int node = i >> 4;
            int gn = base + node;
            int qq = (i & 15) << 2;
            float inv = 1.0f / (float)max(__ldg(&cnt[gn]), 1);
            float4 a = *(const float4*)(agg + (size_t)gn * DD + qq);
            float4 hh = *(const float4*)(h + (size_t)gn * DD + qq);
            a.x *= inv; a.y *= inv; a.z *= inv; a.w *= inv;
            *(float4*)&sIn0[i << 2] = a;
            *(float4*)&sIn1[i << 2] = hh;
        }
        __syncthreads();
        float acc[8];
#pragma unroll
        for (int j = 0; j < 8; j++) acc[j] = 0.f;
#pragma unroll 4
        for (int k = 0; k < 64; k += 4) {
            float w00 = sW0[k * 64 + d], w01 = sW0[(k + 1) * 64 + d];
            float w02 = sW0[(k + 2) * 64 + d], w03 = sW0[(k + 3) * 64 + d];
            float w10 = sW1[k * 64 + d], w11 = sW1[(k + 1) * 64 + d];
            float w12 = sW1[(k + 2) * 64 + d], w13 = sW1[(k + 3) * 64 + d];
#pragma unroll
            for (int j = 0; j < 8; j++) {
                int node = ty + (j << 2);
                float4 a = *(const float4*)&sIn0[node * 64 + k];
                float4 b = *(const float4*)&sIn1[node * 64 + k];
                acc[j] = fmaf(a.x, w00, acc[j]); acc[j] = fmaf(a.y, w01, acc[j]);
                acc[j] = fmaf(a.z, w02, acc[j]); acc[j] = fmaf(a.w, w03, acc[j]);
                acc[j] = fmaf(b.x, w10, acc[j]); acc[j] = fmaf(b.y, w11, acc[j]);
                acc[j] = fmaf(b.z, w12, acc[j]); acc[j] = fmaf(b.w, w13, acc[j]);
            }
        }
        __syncthreads();  // everyone done reading sIn0 before we overwrite it
        // bias + residual, stage pre-LN values into sIn0
#pragma unroll
        for (int j = 0; j < 8; j++) {
            int node = ty + (j << 2);
            sIn0[node * 64 + d] = acc[j] + bd + sIn1[node * 64 + d];
        }
        __syncthreads();
        // LayerNorm + ReLU: warp `wid` handles nodes [wid*4, wid*4+4)
#pragma unroll
        for (int jj = 0; jj < 4; jj++) {
            int node = (wid << 2) + jj;
            int gn = base + node;
            float x0 = sIn0[node * 64 + lane];
            float x1 = sIn0[node * 64 + 32 + lane];
            float s = x0 + x1;
#pragma unroll
            for (int o = 16; o; o >>= 1) s += __shfl_xor_sync(0xffffffffu, s, o);
            float m = s * 0.015625f;
            float e0 = x0 - m, e1 = x1 - m;
            float v = e0 * e0 + e1 * e1;
#pragma unroll
            for (int o = 16; o; o >>= 1) v += __shfl_xor_sync(0xffffffffu, v, o);
            float r = rsqrtf(v * 0.015625f + 1e-5f);
            float y0 = fmaf(e0 * r, gg0, bb0);
            float y1 = fmaf(e1 * r, gg1, bb1);
            out[(size_t)gn * DD + lane] = fmaxf(y0, 0.f);
            out[(size_t)gn * DD + 32 + lane] = fmaxf(y1, 0.f);
        }
    }
}

// ---------------- launch ----------------
extern "C" void kernel_launch(void* const* d_in, const int* in_sizes, int n_in,
                              void* d_out, int out_size) {
    const float* x_user     = (const float*)d_in[0];
    const float* x_item     = (const float*)d_in[1];
    const int*   src_u2i    = (const int*)d_in[2];
    const int*   dst_u2i    = (const int*)d_in[3];
    const int*   src_i2u    = (const int*)d_in[4];
    const int*   dst_i2u    = (const int*)d_in[5];
    const float* W_rel_u2i  = (const float*)d_in[6];
    const float* W_root_u2i = (const float*)d_in[7];
    const float* b_u2i      = (const float*)d_in[8];
    const float* W_rel_i2u  = (const float*)d_in[9];
    const float* W_root_i2u = (const float*)d_in[10];
    const float* b_i2u      = (const float*)d_in[11];
    const float* ln_g_user  = (const float*)d_in[12];
    const float* ln_b_user  = (const float*)d_in[13];
    const float* ln_g_item  = (const float*)d_in[14];
    const float* ln_b_item  = (const float*)d_in[15];
    float* out = (float*)d_out;

    float *p_hu, *p_hi, *p_agg_u, *p_agg_i;
    int *p_cnt_u, *p_cnt_i, *p_off_u, *p_off_i, *p_woff_u, *p_woff_i;
    int *p_ssrc_u2i, *p_ssrc_i2u, *p_bsum_u, *p_bsum_i;
    cudaGetSymbolAddress((void**)&p_hu, g_hu);
    cudaGetSymbolAddress((void**)&p_hi, g_hi);
    cudaGetSymbolAddress((void**)&p_agg_u, g_agg_u);
    cudaGetSymbolAddress((void**)&p_agg_i, g_agg_i);
    cudaGetSymbolAddress((void**)&p_cnt_u, g_cnt_u);
    cudaGetSymbolAddress((void**)&p_cnt_i, g_cnt_i);
    cudaGetSymbolAddress((void**)&p_off_u, g_off_u);
    cudaGetSymbolAddress((void**)&p_off_i, g_off_i);
    cudaGetSymbolAddress((void**)&p_woff_u, g_woff_u);
    cudaGetSymbolAddress((void**)&p_woff_i, g_woff_i);
    cudaGetSymbolAddress((void**)&p_ssrc_u2i, g_ssrc_u2i);
    cudaGetSymbolAddress((void**)&p_ssrc_i2u, g_ssrc_i2u);
    cudaGetSymbolAddress((void**)&p_bsum_u, g_bsum_u);
    cudaGetSymbolAddress((void**)&p_bsum_i, g_bsum_i);

    const int TB = 256;
    const int nbI = (NI + 1023) / 1024;  // 98
    const int nbU = (NU + 1023) / 1024;  // 196

    // --- CSR build (reused by both layers; edge indices are layer-invariant) ---
    zero_int_k<<<(NI + TB - 1) / TB, TB>>>(p_cnt_i, NI);
    zero_int_k<<<(NU + TB - 1) / TB, TB>>>(p_cnt_u, NU);
    count_k<<<(NE + TB - 1) / TB, TB>>>(dst_u2i, p_cnt_i, NE);
    count_k<<<(NE + TB - 1) / TB, TB>>>(dst_i2u, p_cnt_u, NE);
    block_sum_k<<<nbI, 1024>>>(p_cnt_i, p_bsum_i, NI);
    scan_bsum_k<<<1, 1024>>>(p_bsum_i, nbI);
    scan_write_k<<<nbI, 1024>>>(p_cnt_i, p_bsum_i, p_off_i, p_woff_i, NI);
    block_sum_k<<<nbU, 1024>>>(p_cnt_u, p_bsum_u, NU);
    scan_bsum_k<<<1, 1024>>>(p_bsum_u, nbU);
    scan_write_k<<<nbU, 1024>>>(p_cnt_u, p_bsum_u, p_off_u, p_woff_u, NU);
    fill_k<<<(NE + TB - 1) / TB, TB>>>(src_u2i, dst_u2i, p_woff_i, p_ssrc_u2i, NE);
    fill_k<<<(NE + TB - 1) / TB, TB>>>(src_i2u, dst_i2u, p_woff_u, p_ssrc_i2u, NE);

    const int gridAggI = (NI * 16 + TB - 1) / TB;
    const int gridAggU = (NU * 16 + TB - 1) / TB;
    const int gridCompI = 592 < (NI >> 5) ? 592 : (NI >> 5);
    const int gridCompU = 592 < (NU >> 5) ? 592 : (NU >> 5);

    // --- layer 0: read harness inputs, write device scratch ---
    agg_k<<<gridAggI, TB>>>(x_user, p_off_i, p_ssrc_u2i, p_agg_i, NI);
    agg_k<<<gridAggU, TB>>>(x_item, p_off_u, p_ssrc_i2u, p_agg_u, NU);
    compute_k<<<gridCompI, TB>>>(p_agg_i, p_cnt_i, x_item,
                                 W_rel_u2i, W_root_u2i, b_u2i,
                                 ln_g_item, ln_b_item, p_hi, NI);
    compute_k<<<gridCompU, TB>>>(p_agg_u, p_cnt_u, x_user,
                                 W_rel_i2u, W_root_i2u, b_i2u,
                                 ln_g_user, ln_b_user, p_hu, NU);

    // --- layer 1: read scratch, write d_out (users first, then items) ---
    agg_k<<<gridAggI, TB>>>(p_hu, p_off_i, p_ssrc_u2i, p_agg_i, NI);
    agg_k<<<gridAggU, TB>>>(p_hi, p_off_u, p_ssrc_i2u, p_agg_u, NU);
    compute_k<<<gridCompI, TB>>>(p_agg_i, p_cnt_i, p_hi,
                                 W_rel_u2i + 4096, W_root_u2i + 4096, b_u2i + 64,
                                 ln_g_item + 64, ln_b_item + 64,
                                 out + (size_t)NU * DD, NI);
    compute_k<<<gridCompU, TB>>>(p_agg_u, p_cnt_u, p_hu,
                                 W_rel_i2u + 4096, W_root_i2u + 4096, b_i2u + 64,
                                 ln_g_user + 64, ln_b_user + 64,
                                 out, NU);
}

// round 4
// speedup vs baseline: 1.0411x; 1.0411x over previous
#include <cuda_runtime.h>
#include <cuda_fp16.h>
#include <cstdint>

#define NU 200000
#define NI 100000
#define NE 3200000
#define DD 64

// ---------------- device scratch (static; no runtime allocation) ----------------
__device__ float  g_hu[NU * DD];
__device__ float  g_hi[NI * DD];
__device__ __half g_hu16[NU * DD];
__device__ __half g_hi16[NI * DD];
__device__ __half g_xu16[NU * DD];
__device__ __half g_xi16[NI * DD];
__device__ float  g_agg_u[NU * DD];
__device__ float  g_agg_i[NI * DD];
__device__ int    g_cnt_u[NU];
__device__ int    g_cnt_i[NI];
__device__ float  g_inv_u[NU];
__device__ float  g_inv_i[NI];
__device__ int    g_off_u[NU + 1];
__device__ int    g_off_i[NI + 1];
__device__ int    g_woff_u[NU];
__device__ int    g_woff_i[NI];
__device__ int    g_ssrc_u2i[NE];
__device__ int    g_ssrc_i2u[NE];
__device__ int    g_bsum_u[256];
__device__ int    g_bsum_i[256];

// ---------------- small utility kernels ----------------
__global__ void zero_int_k(int* __restrict__ p, int n) {
    int i = blockIdx.x * blockDim.x + threadIdx.x;
    if (i < n) p[i] = 0;
}

__global__ void count_k(const int* __restrict__ dst, int* __restrict__ cnt, int n) {
    for (int i = blockIdx.x * blockDim.x + threadIdx.x; i < n; i += gridDim.x * blockDim.x)
        atomicAdd(&cnt[__ldg(&dst[i])], 1);
}

// fp32 -> fp16 shadow copy (n = element count, multiple of 4)
__global__ void f2h_k(const float* __restrict__ x, __half* __restrict__ y, int n) {
    int idx = (blockIdx.x * blockDim.x + threadIdx.x) << 2;
    if (idx < n) {
        float4 v = *(const float4*)(x + idx);
        __half2 h0 = __floats2half2_rn(v.x, v.y);
        __half2 h1 = __floats2half2_rn(v.z, v.w);
        *(__half2*)(y + idx) = h0;
        *(__half2*)(y + idx + 2) = h1;
    }
}

// ---------------- 3-kernel exclusive scan (counts -> row offsets + inv count) ---
__global__ void block_sum_k(const int* __restrict__ cnt, int* __restrict__ bsum, int n) {
    __shared__ int s[1024];
    int i = blockIdx.x * 1024 + threadIdx.x;
    int v = (i < n) ? cnt[i] : 0;
    s[threadIdx.x] = v;
    __syncthreads();
    for (int st = 512; st > 0; st >>= 1) {
        if (threadIdx.x < st) s[threadIdx.x] += s[threadIdx.x + st];
        __syncthreads();
    }
    if (threadIdx.x == 0) bsum[blockIdx.x] = s[0];
}

__global__ void scan_bsum_k(int* __restrict__ bsum, int nb) {
    __shared__ int s[1024];
    int v = (threadIdx.x < nb) ? bsum[threadIdx.x] : 0;
    s[threadIdx.x] = v;
    __syncthreads();
    for (int o = 1; o < 1024; o <<= 1) {
        int t = (threadIdx.x >= o) ? s[threadIdx.x - o] : 0;
        __syncthreads();
        s[threadIdx.x] += t;
        __syncthreads();
    }
    if (threadIdx.x < nb) bsum[threadIdx.x] = s[threadIdx.x] - v;  // exclusive
}

__global__ void scan_write_k(const int* __restrict__ cnt, const int* __restrict__ bsum,
                             int* __restrict__ off, int* __restrict__ woff,
                             float* __restrict__ inv, int n) {
    __shared__ int s[1024];
    int i = blockIdx.x * 1024 + threadIdx.x;
    int v = (i < n) ? cnt[i] : 0;
    s[threadIdx.x] = v;
    __syncthreads();
    for (int o = 1; o < 1024; o <<= 1) {
        int t = (threadIdx.x >= o) ? s[threadIdx.x - o] : 0;
        __syncthreads();
        s[threadIdx.x] += t;
        __syncthreads();
    }
    int excl = s[threadIdx.x] - v + bsum[blockIdx.x];
    if (i < n) {
        off[i] = excl; woff[i] = excl;
        inv[i] = 1.0f / (float)max(v, 1);
    }
    if (i == n - 1) off[n] = excl + v;
}

__global__ void fill_k(const int* __restrict__ src, const int* __restrict__ dst,
                       int* __restrict__ woff, int* __restrict__ ssrc, int n) {
    for (int i = blockIdx.x * blockDim.x + threadIdx.x; i < n; i += gridDim.x * blockDim.x) {
        int d = __ldg(&dst[i]);
        int p = atomicAdd(&woff[d], 1);
        ssrc[p] = __ldg(&src[i]);
    }
}

// ---------------- fp16 aggregation (gather at destination; fp32 accumulate) ----
// 16 threads per destination node; each owns 4 halves (8 bytes) of the 64-dim row.
__global__ void agg16_k(const __half* __restrict__ h16, const int* __restrict__ roff,
                        const int* __restrict__ ssrc, float* __restrict__ agg, int n) {
    int t = blockIdx.x * blockDim.x + threadIdx.x;
    int node = t >> 4;
    if (node >= n) return;
    int q = (t & 15) << 2;  // half offset
    int b0 = __ldg(&roff[node]), b1 = __ldg(&roff[node + 1]);
    float ax = 0.f, ay = 0.f, az = 0.f, aw = 0.f;
    int i = b0;
    for (; i + 4 <= b1; i += 4) {
        int s0 = __ldg(&ssrc[i]),     s1 = __ldg(&ssrc[i + 1]);
        int s2 = __ldg(&ssrc[i + 2]), s3 = __ldg(&ssrc[i + 3]);
        uint2 v0 = *(const uint2*)(h16 + (size_t)s0 * DD + q);
        uint2 v1 = *(const uint2*)(h16 + (size_t)s1 * DD + q);
        uint2 v2 = *(const uint2*)(h16 + (size_t)s2 * DD + q);
        uint2 v3 = *(const uint2*)(h16 + (size_t)s3 * DD + q);
        float2 f;
        f = __half22float2(*(__half2*)&v0.x); ax += f.x; ay += f.y;
        f = __half22float2(*(__half2*)&v0.y); az += f.x; aw += f.y;
        f = __half22float2(*(__half2*)&v1.x); ax += f.x; ay += f.y;
        f = __half22float2(*(__half2*)&v1.y); az += f.x; aw += f.y;
        f = __half22float2(*(__half2*)&v2.x); ax += f.x; ay += f.y;
        f = __half22float2(*(__half2*)&v2.y); az += f.x; aw += f.y;
        f = __half22float2(*(__half2*)&v3.x); ax += f.x; ay += f.y;
        f = __half22float2(*(__half2*)&v3.y); az += f.x; aw += f.y;
    }
    for (; i < b1; i++) {
        int s = __ldg(&ssrc[i]);
        uint2 v = *(const uint2*)(h16 + (size_t)s * DD + q);
        float2 f;
        f = __half22float2(*(__half2*)&v.x); ax += f.x; ay += f.y;
        f = __half22float2(*(__half2*)&v.y); az += f.x; aw += f.y;
    }
    *(float4*)(agg + (size_t)node * DD + q) = make_float4(ax, ay, az, aw);
}

// ---------------- fused GEMM (FFMA2) + bias + LN + ReLU --------------------------
// out = relu(LN([agg*inv , h] @ [Wrel ; Wroot+I] + b))    (residual folded into W)
// Tile = 32 nodes. Thread (d = tid&63, ty = tid>>6) computes 8 nodes (4 f32x2 pairs).
// Dynamic smem: sW[128*64] fp32 (32KB) + sInT[128*36] (18KB); sOut aliases sInT.
#define SW_FLOATS   (128 * 64)
#define SINT_STRIDE 36
#define SINT_FLOATS (128 * SINT_STRIDE)
#define COMP_SMEM   ((SW_FLOATS + SINT_FLOATS) * 4)

__global__ __launch_bounds__(256) void compute2_k(
    const float* __restrict__ agg, const float* __restrict__ inv,
    const float* __restrict__ h,
    const float* __restrict__ Wrel, const float* __restrict__ Wroot,
    const float* __restrict__ bias, const float* __restrict__ gam,
    const float* __restrict__ bet,
    float* __restrict__ out, __half* __restrict__ out16, int n) {
    extern __shared__ float smem[];
    float* sW   = smem;
    float* sInT = smem + SW_FLOATS;
    float* sOut = sInT;  // alias: rows 0..56 of sInT, reused post-mainloop
    int tid = threadIdx.x;

    // load weights: rows 0..63 = Wrel, rows 64..127 = Wroot + I
    for (int i = tid; i < SW_FLOATS; i += 256) {
        if (i < 4096) {
            sW[i] = Wrel[i];
        } else {
            int j = i - 4096;
            float w = Wroot[j];
            if ((j >> 6) == (j & 63)) w += 1.0f;
            sW[i] = w;
        }
    }

    int d = tid & 63;
    int ty = tid >> 6;
    float bd = __ldg(&bias[d]);
    int lane = tid & 31, wid = tid >> 5;
    float gg0 = __ldg(&gam[lane]), gg1 = __ldg(&gam[lane + 32]);
    float bb0 = __ldg(&bet[lane]), bb1 = __ldg(&bet[lane + 32]);
    int ntile = n >> 5;

    for (int tile = blockIdx.x; tile < ntile; tile += gridDim.x) {
        int base = tile << 5;
        __syncthreads();  // sW ready (first iter) / sOut consumed (later iters)
        // stage transposed: sInT[k][node], k 0..63 = agg*inv, 64..127 = h
        for (int i = tid; i < 512; i += 256) {
            int node = i >> 4;
            int gn = base + node;
            int qq = (i & 15) << 2;
            float iv = __ldg(&inv[gn]);
            float4 a  = *(const float4*)(agg + (size_t)gn * DD + qq);
            float4 hh = *(const float4*)(h + (size_t)gn * DD + qq);
            sInT[(qq + 0) * SINT_STRIDE + node] = a.x * iv;
            sInT[(qq + 1) * SINT_STRIDE + node] = a.y * iv;
            sInT[(qq + 2) * SINT_STRIDE + node] = a.z * iv;
            sInT[(qq + 3) * SINT_STRIDE + node] = a.w * iv;
            sInT[(64 + qq + 0) * SINT_STRIDE + node] = hh.x;
            sInT[(64 + qq + 1) * SINT_STRIDE + node] = hh.y;
            sInT[(64 + qq + 2) * SINT_STRIDE + node] = hh.z;
            sInT[(64 + qq + 3) * SINT_STRIDE + node] = hh.w;
        }
        __syncthreads();

        unsigned long long acc0 = 0ull, acc1 = 0ull, acc2 = 0ull, acc3 = 0ull;
        const float* rowp = &sInT[(ty << 3)];
#pragma unroll 16
        for (int k = 0; k < 128; k++) {
            float w = sW[k * 64 + d];
            unsigned long long w2;
            asm("mov.b64 %0, {%1, %1};" : "=l"(w2) : "f"(w));
            ulonglong2 A = *(const ulonglong2*)(rowp + k * SINT_STRIDE);
            ulonglong2 B = *(const ulonglong2*)(rowp + k * SINT_STRIDE + 4);
            asm("fma.rn.f32x2 %0, %1, %2, %0;" : "+l"(acc0) : "l"(A.x), "l"(w2));
            asm("fma.rn.f32x2 %0, %1, %2, %0;" : "+l"(acc1) : "l"(A.y), "l"(w2));
            asm("fma.rn.f32x2 %0, %1, %2, %0;" : "+l"(acc2) : "l"(B.x), "l"(w2));
            asm("fma.rn.f32x2 %0, %1, %2, %0;" : "+l"(acc3) : "l"(B.y), "l"(w2));
        }
        __syncthreads();  // done reading sInT rows 0..63 -> safe to write sOut alias

        {
            float lo, hi;
            int n0 = ty << 3;
            asm("mov.b64 {%0, %1}, %2;" : "=f"(lo), "=f"(hi) : "l"(acc0));
            sOut[(n0 + 0) * 64 + d] = lo + bd; sOut[(n0 + 1) * 64 + d] = hi + bd;
            asm("mov.b64 {%0, %1}, %2;" : "=f"(lo), "=f"(hi) : "l"(acc1));
            sOut[(n0 + 2) * 64 + d] = lo + bd; sOut[(n0 + 3) * 64 + d] = hi + bd;
            asm("mov.b64 {%0, %1}, %2;" : "=f"(lo), "=f"(hi) : "l"(acc2));
            sOut[(n0 + 4) * 64 + d] = lo + bd; sOut[(n0 + 5) * 64 + d] = hi + bd;
            asm("mov.b64 {%0, %1}, %2;" : "=f"(lo), "=f"(hi) : "l"(acc3));
            sOut[(n0 + 6) * 64 + d] = lo + bd; sOut[(n0 + 7) * 64 + d] = hi + bd;
        }
        __syncthreads();

        // LayerNorm + ReLU: warp `wid` handles nodes [wid*4, wid*4+4)
#pragma unroll
        for (int jj = 0; jj < 4; jj++) {
            int node = (wid << 2) + jj;
            int gn = base + node;
            float x0 = sOut[node * 64 + lane];
            float x1 = sOut[node * 64 + 32 + lane];
            float s = x0 + x1;
#pragma unroll
            for (int o = 16; o; o >>= 1) s += __shfl_xor_sync(0xffffffffu, s, o);
            float m = s * 0.015625f;
            float e0 = x0 - m, e1 = x1 - m;
            float v = e0 * e0 + e1 * e1;
#pragma unroll
            for (int o = 16; o; o >>= 1) v += __shfl_xor_sync(0xffffffffu, v, o);
            float r = rsqrtf(v * 0.015625f + 1e-5f);
            float y0 = fmaxf(fmaf(e0 * r, gg0, bb0), 0.f);
            float y1 = fmaxf(fmaf(e1 * r, gg1, bb1), 0.f);
            out[(size_t)gn * DD + lane] = y0;
            out[(size_t)gn * DD + 32 + lane] = y1;
            if (out16) {
                out16[(size_t)gn * DD + lane] = __float2half_rn(y0);
                out16[(size_t)gn * DD + 32 + lane] = __float2half_rn(y1);
            }
        }
    }
}

// ---------------- launch ----------------
extern "C" void kernel_launch(void* const* d_in, const int* in_sizes, int n_in,
                              void* d_out, int out_size) {
    const float* x_user     = (const float*)d_in[0];
    const float* x_item     = (const float*)d_in[1];
    const int*   src_u2i    = (const int*)d_in[2];
    const int*   dst_u2i    = (const int*)d_in[3];
    const int*   src_i2u    = (const int*)d_in[4];
    const int*   dst_i2u    = (const int*)d_in[5];
    const float* W_rel_u2i  = (const float*)d_in[6];
    const float* W_root_u2i = (const float*)d_in[7];
    const float* b_u2i      = (const float*)d_in[8];
    const float* W_rel_i2u  = (const float*)d_in[9];
    const float* W_root_i2u = (const float*)d_in[10];
    const float* b_i2u      = (const float*)d_in[11];
    const float* ln_g_user  = (const float*)d_in[12];
    const float* ln_b_user  = (const float*)d_in[13];
    const float* ln_g_item  = (const float*)d_in[14];
    const float* ln_b_item  = (const float*)d_in[15];
    float* out = (float*)d_out;

    float *p_hu, *p_hi, *p_agg_u, *p_agg_i, *p_inv_u, *p_inv_i;
    __half *p_hu16, *p_hi16, *p_xu16, *p_xi16;
    int *p_cnt_u, *p_cnt_i, *p_off_u, *p_off_i, *p_woff_u, *p_woff_i;
    int *p_ssrc_u2i, *p_ssrc_i2u, *p_bsum_u, *p_bsum_i;
    cudaGetSymbolAddress((void**)&p_hu, g_hu);
    cudaGetSymbolAddress((void**)&p_hi, g_hi);
    cudaGetSymbolAddress((void**)&p_hu16, g_hu16);
    cudaGetSymbolAddress((void**)&p_hi16, g_hi16);
    cudaGetSymbolAddress((void**)&p_xu16, g_xu16);
    cudaGetSymbolAddress((void**)&p_xi16, g_xi16);
    cudaGetSymbolAddress((void**)&p_agg_u, g_agg_u);
    cudaGetSymbolAddress((void**)&p_agg_i, g_agg_i);
    cudaGetSymbolAddress((void**)&p_inv_u, g_inv_u);
    cudaGetSymbolAddress((void**)&p_inv_i, g_inv_i);
    cudaGetSymbolAddress((void**)&p_cnt_u, g_cnt_u);
    cudaGetSymbolAddress((void**)&p_cnt_i, g_cnt_i);
    cudaGetSymbolAddress((void**)&p_off_u, g_off_u);
    cudaGetSymbolAddress((void**)&p_off_i, g_off_i);
    cudaGetSymbolAddress((void**)&p_woff_u, g_woff_u);
    cudaGetSymbolAddress((void**)&p_woff_i, g_woff_i);
    cudaGetSymbolAddress((void**)&p_ssrc_u2i, g_ssrc_u2i);
    cudaGetSymbolAddress((void**)&p_ssrc_i2u, g_ssrc_i2u);
    cudaGetSymbolAddress((void**)&p_bsum_u, g_bsum_u);
    cudaGetSymbolAddress((void**)&p_bsum_i, g_bsum_i);

    cudaFuncSetAttribute(compute2_k, cudaFuncAttributeMaxDynamicSharedMemorySize,
                         COMP_SMEM);

    const int TB = 256;
    const int nbI = (NI + 1023) / 1024;  // 98
    const int nbU = (NU + 1023) / 1024;  // 196

    // --- CSR build (edge indices are layer-invariant) ---
    zero_int_k<<<(NI + TB - 1) / TB, TB>>>(p_cnt_i, NI);
    zero_int_k<<<(NU + TB - 1) / TB, TB>>>(p_cnt_u, NU);
    count_k<<<(NE + TB - 1) / TB, TB>>>(dst_u2i, p_cnt_i, NE);
    count_k<<<(NE + TB - 1) / TB, TB>>>(dst_i2u, p_cnt_u, NE);
    block_sum_k<<<nbI, 1024>>>(p_cnt_i, p_bsum_i, NI);
    scan_bsum_k<<<1, 1024>>>(p_bsum_i, nbI);
    scan_write_k<<<nbI, 1024>>>(p_cnt_i, p_bsum_i, p_off_i, p_woff_i, p_inv_i, NI);
    block_sum_k<<<nbU, 1024>>>(p_cnt_u, p_bsum_u, NU);
    scan_bsum_k<<<1, 1024>>>(p_bsum_u, nbU);
    scan_write_k<<<nbU, 1024>>>(p_cnt_u, p_bsum_u, p_off_u, p_woff_u, p_inv_u, NU);
    fill_k<<<(NE + TB - 1) / TB, TB>>>(src_u2i, dst_u2i, p_woff_i, p_ssrc_u2i, NE);
    fill_k<<<(NE + TB - 1) / TB, TB>>>(src_i2u, dst_i2u, p_woff_u, p_ssrc_i2u, NE);

    // fp16 shadows of the layer-0 inputs
    f2h_k<<<(NU * DD / 4 + TB - 1) / TB, TB>>>(x_user, p_xu16, NU * DD);
    f2h_k<<<(NI * DD / 4 + TB - 1) / TB, TB>>>(x_item, p_xi16, NI * DD);

    const int gridAggI = (NI * 16 + TB - 1) / TB;
    const int gridAggU = (NU * 16 + TB - 1) / TB;
    const int gridCompI = 592 < (NI >> 5) ? 592 : (NI >> 5);
    const int gridCompU = 592 < (NU >> 5) ? 592 : (NU >> 5);

    // --- layer 0 ---
    agg16_k<<<gridAggI, TB>>>(p_xu16, p_off_i, p_ssrc_u2i, p_agg_i, NI);
    agg16_k<<<gridAggU, TB>>>(p_xi16, p_off_u, p_ssrc_i2u, p_agg_u, NU);
    compute2_k<<<gridCompI, TB, COMP_SMEM>>>(p_agg_i, p_inv_i, x_item,
                                             W_rel_u2i, W_root_u2i, b_u2i,
                                             ln_g_item, ln_b_item, p_hi, p_hi16, NI);
    compute2_k<<<gridCompU, TB, COMP_SMEM>>>(p_agg_u, p_inv_u, x_user,
                                             W_rel_i2u, W_root_i2u, b_i2u,
                                             ln_g_user, ln_b_user, p_hu, p_hu16, NU);

    // --- layer 1 (writes d_out: users first, then items) ---
    agg16_k<<<gridAggI, TB>>>(p_hu16, p_off_i, p_ssrc_u2i, p_agg_i, NI);
    agg16_k<<<gridAggU, TB>>>(p_hi16, p_off_u, p_ssrc_i2u, p_agg_u, NU);
    compute2_k<<<gridCompI, TB, COMP_SMEM>>>(p_agg_i, p_inv_i, p_hi,
                                             W_rel_u2i + 4096, W_root_u2i + 4096,
                                             b_u2i + 64, ln_g_item + 64, ln_b_item + 64,
                                             out + (size_t)NU * DD, (__half*)0, NI);
    compute2_k<<<gridCompU, TB, COMP_SMEM>>>(p_agg_u, p_inv_u, p_hu,
                                             W_rel_i2u + 4096, W_root_i2u + 4096,
                                             b_i2u + 64, ln_g_user + 64, ln_b_user + 64,
                                             out, (__half*)0, NU);
}